// round 14
// baseline (speedup 1.0000x reference)
#include <cuda_runtime.h>
#include <cuda_fp16.h>
#include <math.h>

#define B_  2
#define S_  2048
#define D_  1024
#define H_  16
#define DK_ 64
#define M_  (B_*S_)   // 4096

// Scratch (device globals — no allocation allowed).
__device__ __half g_hq[M_*D_];      // fp16 copies of inputs
__device__ __half g_hk[M_*D_];
__device__ __half g_hv[M_*D_];
__device__ __half g_hw0[D_*D_];     // fp16 copies of weights
__device__ __half g_hw1[D_*D_];
__device__ __half g_hw2[D_*D_];
__device__ __half g_hw3[D_*D_];
// Projected tensors (fp16). g_q pre-scaled by 0.125*log2(e). g_q/g_k: [b,h,s,d].
// g_v: d-major [b,h,d,s] (s contiguous -> s-pair halves form one 32-bit word).
__device__ __half g_q[B_*H_*S_*DK_];
__device__ __half g_k[B_*H_*S_*DK_];
__device__ __half g_v[B_*H_*S_*DK_];
__device__ __half g_ax[M_*D_];      // attention output (fp16)
__device__ unsigned char g_mflag[B_*16*32];

#define QSCALE 0.180336880f   // 0.125 * log2(e); scores become log2-domain

// ---------------------------------------------------------------------------
__device__ __forceinline__ unsigned pk2(float lo, float hi) {
    __half2 h = __floats2half2_rn(lo, hi);
    return *reinterpret_cast<unsigned*>(&h);
}

__device__ __forceinline__ float ex2(float x) {
    float y;
    asm("ex2.approx.f32 %0, %1;" : "=f"(y) : "f"(x));
    return y;
}

__device__ __forceinline__ void mma16(float (&c)[4],
                                      unsigned a0, unsigned a1, unsigned a2, unsigned a3,
                                      unsigned b0, unsigned b1) {
    asm volatile(
        "mma.sync.aligned.m16n8k16.row.col.f32.f16.f16.f32 "
        "{%0,%1,%2,%3}, {%4,%5,%6,%7}, {%8,%9}, {%0,%1,%2,%3};"
        : "+f"(c[0]), "+f"(c[1]), "+f"(c[2]), "+f"(c[3])
        : "r"(a0), "r"(a1), "r"(a2), "r"(a3), "r"(b0), "r"(b1));
}

__device__ __forceinline__ void ldsm4(unsigned& r0, unsigned& r1, unsigned& r2, unsigned& r3,
                                      unsigned addr) {
    asm volatile("ldmatrix.sync.aligned.m8n8.x4.shared.b16 {%0,%1,%2,%3}, [%4];"
        : "=r"(r0), "=r"(r1), "=r"(r2), "=r"(r3) : "r"(addr));
}

// .cg = L2-only; these loads are consumed from smem, keep them out of L1.
#define CPA16(dst, src) asm volatile("cp.async.cg.shared.global [%0], [%1], 16;" :: "r"(dst), "l"(src))
#define CPCOMMIT()      asm volatile("cp.async.commit_group;" ::: "memory")
#define CPWAIT0()       asm volatile("cp.async.wait_group 0;" ::: "memory")
#define CPWAIT1()       asm volatile("cp.async.wait_group 1;" ::: "memory")

// ---------------------------------------------------------------------------
// prep: fp32 -> fp16 convert only (mask scan moved into gemm_qkv z=3 slice).
// ---------------------------------------------------------------------------
__global__ __launch_bounds__(256)
void prep_all(const float* __restrict__ q, const float* __restrict__ k,
              const float* __restrict__ v,
              const float* __restrict__ W0, const float* __restrict__ W1,
              const float* __restrict__ W2, const float* __restrict__ W3)
{
    const size_t i4 = (size_t)blockIdx.x * 256 + threadIdx.x;
    const size_t off = i4 * 4;
    const size_t IN = (size_t)M_ * D_;
    const size_t WN = (size_t)D_ * D_;
    const float* src; __half* dst; size_t o;
    if      (off < IN)            { src = q;  dst = g_hq;  o = off; }
    else if (off < 2*IN)          { src = k;  dst = g_hk;  o = off - IN; }
    else if (off < 3*IN)          { src = v;  dst = g_hv;  o = off - 2*IN; }
    else if (off < 3*IN + WN)     { src = W0; dst = g_hw0; o = off - 3*IN; }
    else if (off < 3*IN + 2*WN)   { src = W1; dst = g_hw1; o = off - 3*IN - WN; }
    else if (off < 3*IN + 3*WN)   { src = W2; dst = g_hw2; o = off - 3*IN - 2*WN; }
    else                          { src = W3; dst = g_hw3; o = off - 3*IN - 3*WN; }
    float4 vv = *(const float4*)(src + o);
    *(uint2*)(dst + o) = make_uint2(pk2(vv.x, vv.y), pk2(vv.z, vv.w));
}

// ---------------------------------------------------------------------------
// FP16 NT GEMM, cp.async.cg 3-stage pipeline, K-chunk 64 (16 chunks).
// MODE: 0 = fp32 [m][n]; 1 = Q half *QSCALE; 2 = K half; 3 = V d-major [b,h,d,s].
// ---------------------------------------------------------------------------
#define GW 36                                       // 32 data words + 4 pad
#define GST (128*GW)                                // words per tile-stage
#define GNS 3
#define GEMM_SMEM (2*GNS*GST*(int)sizeof(unsigned)) // 110592 B

template<int MODE>
__device__ __forceinline__ void gemm_body(
    const __half* __restrict__ X, const __half* __restrict__ W,
    const float* __restrict__ bias, void* outp)
{
    extern __shared__ unsigned gsm[];
    unsigned* As = gsm;
    unsigned* Bs = gsm + GNS * GST;

    const int tid = threadIdx.x;
    const int lane = tid & 31, wid = tid >> 5;
    const int warpM = wid >> 2, warpN = wid & 3;
    const int m0 = blockIdx.y * 128, n0 = blockIdx.x * 128;
    const int g = lane >> 2, t = lane & 3;

    const unsigned asb = (unsigned)__cvta_generic_to_shared(As);
    const unsigned bsb = (unsigned)__cvta_generic_to_shared(Bs);

    const int selA = lane >> 3;
    const int rA = (lane & 7) + ((selA & 1) << 3);
    const int cA = selA >> 1;
    const int selB = lane >> 3;
    const int rB = lane & 7;
    const int ntOff = selB >> 1, kcB = selB & 1;

    float acc[4][4][4] = {};

    auto load_stage = [&](int c0, int st) {
        #pragma unroll
        for (int i = 0; i < 4; ++i) {
            const int idx = tid + i * 256;             // 0..1023 chunks / matrix
            const int r = idx >> 3, ch = idx & 7;
            const unsigned doff = (unsigned)(st * GST + r * GW + ch * 4) * 4;
            CPA16(asb + doff, X + (size_t)(m0 + r) * D_ + c0 * 64 + ch * 8);
            CPA16(bsb + doff, W + (size_t)(n0 + r) * D_ + c0 * 64 + ch * 8);
        }
        CPCOMMIT();
    };

    load_stage(0, 0);
    load_stage(1, 1);

    for (int c0 = 0; c0 < 16; ++c0) {
        if (c0 < 14) CPWAIT1(); else CPWAIT0();     // chunk c0 resident
        __syncthreads();
        if (c0 + 2 < 16) {
            int st = c0 + 2; while (st >= GNS) st -= GNS;   // (c0+2) % 3
            load_stage(c0 + 2, st);
        }

        int cs = c0; while (cs >= GNS) cs -= GNS;           // c0 % 3
        const unsigned ab = asb + (unsigned)(cs * GST) * 4;
        const unsigned bb = bsb + (unsigned)(cs * GST) * 4;

        #pragma unroll
        for (int kb = 0; kb < 4; ++kb) {
            unsigned af[4][4], bf[4][2];
            #pragma unroll
            for (int mt = 0; mt < 4; ++mt) {
                const unsigned addr = ab +
                    (unsigned)((warpM * 64 + mt * 16 + rA) * GW + cA * 4 + kb * 8) * 4;
                ldsm4(af[mt][0], af[mt][1], af[mt][2], af[mt][3], addr);
            }
            #pragma unroll
            for (int np = 0; np < 2; ++np) {
                const unsigned addr = bb +
                    (unsigned)((warpN * 32 + (np * 2 + ntOff) * 8 + rB) * GW + kcB * 4 + kb * 8) * 4;
                ldsm4(bf[np*2][0], bf[np*2][1], bf[np*2+1][0], bf[np*2+1][1], addr);
            }
            #pragma unroll
            for (int mt = 0; mt < 4; ++mt)
                #pragma unroll
                for (int nt = 0; nt < 4; ++nt)
                    mma16(acc[mt][nt], af[mt][0], af[mt][1], af[mt][2], af[mt][3],
                          bf[nt][0], bf[nt][1]);
        }
    }

    #pragma unroll
    for (int mt = 0; mt < 4; ++mt) {
        const int r_lo = m0 + warpM * 64 + mt * 16 + g;
        const int r_hi = r_lo + 8;
        #pragma unroll
        for (int nt = 0; nt < 4; ++nt) {
            const int col = n0 + warpN * 32 + nt * 8 + t * 2;
            const float bv0 = bias[col], bv1 = bias[col + 1];
            float v0 = acc[mt][nt][0] + bv0, v1 = acc[mt][nt][1] + bv1;
            float v2 = acc[mt][nt][2] + bv0, v3 = acc[mt][nt][3] + bv1;
            if (MODE == 0) {
                float* out = (float*)outp;
                *(float2*)&out[(size_t)r_lo * D_ + col] = make_float2(v0, v1);
                *(float2*)&out[(size_t)r_hi * D_ + col] = make_float2(v2, v3);
            } else {
                const int h = col >> 6, d = col & 63;
                if (MODE == 1) { v0 *= QSCALE; v1 *= QSCALE; v2 *= QSCALE; v3 *= QSCALE; }
                const int s_lo = r_lo & 2047, s_hi = r_hi & 2047;
                const size_t bh_lo = (size_t)((r_lo >> 11) * H_ + h);
                const size_t bh_hi = (size_t)((r_hi >> 11) * H_ + h);
                if (MODE == 1 || MODE == 2) {
                    unsigned* out = (unsigned*)outp;
                    out[((bh_lo * S_ + s_lo) * DK_ + d) >> 1] = pk2(v0, v1);
                    out[((bh_hi * S_ + s_hi) * DK_ + d) >> 1] = pk2(v2, v3);
                } else {   // MODE 3: V d-major [b,h,d,s]
                    __half* out = (__half*)outp;
                    const size_t base_lo = bh_lo * (S_ * DK_);
                    const size_t base_hi = bh_hi * (S_ * DK_);
                    out[base_lo + (size_t)d       * S_ + s_lo] = __float2half_rn(v0);
                    out[base_lo + (size_t)(d + 1) * S_ + s_lo] = __float2half_rn(v1);
                    out[base_hi + (size_t)d       * S_ + s_hi] = __float2half_rn(v2);
                    out[base_hi + (size_t)(d + 1) * S_ + s_hi] = __float2half_rn(v3);
                }
            }
        }
    }
}

// z in [0,2]: Q/K/V projections. z==3: mask tile scan (4 tiles per block),
// overlapped with the tensor-bound GEMM wave.
__global__ __launch_bounds__(256, 2)
void gemm_qkv(const float* __restrict__ b0, const float* __restrict__ b1,
              const float* __restrict__ b2, const int* __restrict__ mask)
{
    const int z = blockIdx.z;
    if (z == 3) {
        const int base_idx = (blockIdx.y * 8 + blockIdx.x) * 4;
        for (int i = 0; i < 4; ++i) {
            const int tile = base_idx + i;             // b*512 + qt*32 + kt
            const int kt = tile & 31, qt = (tile >> 5) & 15, b = tile >> 9;
            const int* basep = mask + ((size_t)(b * S_) + qt * 128) * S_ + kt * 64;
            int ok = 1;
            for (int j = threadIdx.x; j < 2048; j += 256) {
                const int r = j >> 4, c = (j & 15) * 4;
                int4 vv = *(const int4*)(basep + (size_t)r * S_ + c);
                ok &= (vv.x != 0) & (vv.y != 0) & (vv.z != 0) & (vv.w != 0);
            }
            ok = __syncthreads_and(ok);
            if (threadIdx.x == 0) g_mflag[tile] = (unsigned char)ok;
        }
        return;
    }
    if (z == 0)      gemm_body<1>(g_hq, g_hw0, b0, (void*)g_q);
    else if (z == 1) gemm_body<2>(g_hk, g_hw1, b1, (void*)g_k);
    else             gemm_body<3>(g_hv, g_hw2, b2, (void*)g_v);
}

__global__ __launch_bounds__(256, 2)
void gemm_fin(const float* __restrict__ bias, float* __restrict__ out)
{
    gemm_body<0>(g_ax, g_hw3, bias, (void*)out);
}

// ---------------------------------------------------------------------------
// Flash attention, fp16 m16n8k16, log2-domain, 2-stage cp.async.cg.
// 4 warps x 32 q-rows; k-columns processed in two halves of 32 so the live
// s-fragment set halves (32 regs) -> fits 3 CTAs/SM (12 warps).
// ---------------------------------------------------------------------------
#define KST 36
#define VST 36
#define KSTG (64*KST)
#define VSTG (64*VST)

__global__ __launch_bounds__(128, 3)
void attn_tc(const int* __restrict__ mask)
{
    __shared__ unsigned Ks[2 * KSTG];
    __shared__ unsigned Vs[2 * VSTG];

    const int qt = blockIdx.x, h = blockIdx.y, b = blockIdx.z;
    const int q0 = qt * 128;
    const int tid = threadIdx.x, lane = tid & 31, w = tid >> 5;   // w: 0..3
    const int g = lane >> 2, t = lane & 3;
    const unsigned FULL = 0xffffffffu;

    const unsigned* Qw = (const unsigned*)g_q + ((size_t)(b * H_ + h) * S_ + q0 + w * 32) * 32;
    const unsigned* Kw = (const unsigned*)g_k + (size_t)(b * H_ + h) * S_ * 32;
    const unsigned* Vw = (const unsigned*)g_v + (size_t)(b * H_ + h) * S_ * 32;

    const unsigned ksb = (unsigned)__cvta_generic_to_shared(Ks);
    const unsigned vsb = (unsigned)__cvta_generic_to_shared(Vs);

    const int lrow = lane & 7;
    const int lmat = lane >> 3;
    const int ntof = lmat >> 1;
    const int bsel = lmat & 1;
    unsigned kfb[4], vfb[4];
    #pragma unroll
    for (int np = 0; np < 4; ++np) {
        kfb[np] = ksb + (unsigned)(((np * 16 + ntof * 8 + lrow) * KST + bsel * 4) * 4);
        vfb[np] = vsb + (unsigned)(((np * 16 + ntof * 8 + lrow) * VST + bsel * 4) * 4);
    }

    const int fbase = (b * 16 + qt) * 32;
    unsigned mflags[8];
    {
        const uint4* mfp = (const uint4*)&g_mflag[fbase];
        uint4 f0 = mfp[0], f1 = mfp[1];
        mflags[0] = f0.x; mflags[1] = f0.y; mflags[2] = f0.z; mflags[3] = f0.w;
        mflags[4] = f1.x; mflags[5] = f1.y; mflags[6] = f1.z; mflags[7] = f1.w;
    }

    unsigned qa[2][4][4];
    #pragma unroll
    for (int rb = 0; rb < 2; ++rb) {
        #pragma unroll
        for (int kb = 0; kb < 4; ++kb) {
            qa[rb][kb][0] = Qw[(size_t)(rb * 16 + g    ) * 32 + kb * 8 + t];
            qa[rb][kb][1] = Qw[(size_t)(rb * 16 + g + 8) * 32 + kb * 8 + t];
            qa[rb][kb][2] = Qw[(size_t)(rb * 16 + g    ) * 32 + kb * 8 + t + 4];
            qa[rb][kb][3] = Qw[(size_t)(rb * 16 + g + 8) * 32 + kb * 8 + t + 4];
        }
    }

    float o[2][8][4] = {};
    float L_lo[2] = {0.f, 0.f}, L_hi[2] = {0.f, 0.f};

    auto load_tile = [&](int kt, int st) {
        #pragma unroll
        for (int i = 0; i < 4; ++i) {
            const int idx = tid + i * 128;
            const int r = idx >> 3, ch = idx & 7;
            CPA16(ksb + (unsigned)((st * KSTG + r * KST + ch * 4) * 4),
                  Kw + (size_t)(kt * 64 + r) * 32 + ch * 4);
        }
        #pragma unroll
        for (int i = 0; i < 4; ++i) {
            const int idx = tid + i * 128;
            const int r = idx >> 3, ch = idx & 7;
            CPA16(vsb + (unsigned)((st * VSTG + r * VST + ch * 4) * 4),
                  Vw + (size_t)r * (S_ / 2) + kt * 32 + ch * 4);
        }
        CPCOMMIT();
    };

    load_tile(0, 0);

    for (int kt = 0; kt < 32; ++kt) {
        CPWAIT0();
        __syncthreads();
        if (kt < 31) load_tile(kt + 1, (kt + 1) & 1);

        const unsigned kof = (unsigned)((kt & 1) * KSTG * 4);
        const unsigned vof = (unsigned)((kt & 1) * VSTG * 4);
        const bool masked = ((mflags[kt >> 2] >> ((kt & 3) * 8)) & 0xffu) == 0;

        #pragma unroll
        for (int hf = 0; hf < 2; ++hf) {
            // S = Q K^T for k-columns [hf*32, hf*32+32)
            float s[2][4][4] = {};
            #pragma unroll
            for (int kb = 0; kb < 4; ++kb) {
                #pragma unroll
                for (int npl = 0; npl < 2; ++npl) {
                    const int np = 2 * hf + npl;
                    unsigned b00, b01, b10, b11;
                    ldsm4(b00, b01, b10, b11, kfb[np] + kof + kb * 32);
                    #pragma unroll
                    for (int rb = 0; rb < 2; ++rb) {
                        mma16(s[rb][2*npl    ], qa[rb][kb][0], qa[rb][kb][1],
                              qa[rb][kb][2], qa[rb][kb][3], b00, b01);
                        mma16(s[rb][2*npl + 1], qa[rb][kb][0], qa[rb][kb][1],
                              qa[rb][kb][2], qa[rb][kb][3], b10, b11);
                    }
                }
            }

            if (masked) {
                const int* mb = mask + (size_t)b * S_ * S_;
                #pragma unroll
                for (int rb = 0; rb < 2; ++rb) {
                    const int r_lo = q0 + w * 32 + rb * 16 + g, r_hi = r_lo + 8;
                    #pragma unroll
                    for (int l = 0; l < 4; ++l) {
                        const int col = kt * 64 + (hf * 4 + l) * 8 + t * 2;
                        if (mb[(size_t)r_lo * S_ + col    ] == 0) s[rb][l][0] = -1.0e9f;
                        if (mb[(size_t)r_lo * S_ + col + 1] == 0) s[rb][l][1] = -1.0e9f;
                        if (mb[(size_t)r_hi * S_ + col    ] == 0) s[rb][l][2] = -1.0e9f;
                        if (mb[(size_t)r_hi * S_ + col + 1] == 0) s[rb][l][3] = -1.0e9f;
                    }
                }
            }

            // exp2 + PV for s-positions [hf*32, hf*32+32)
            #pragma unroll
            for (int kbl = 0; kbl < 2; ++kbl) {
                unsigned a0[2], a1[2], a2[2], a3[2];
                #pragma unroll
                for (int rb = 0; rb < 2; ++rb) {
                    const float p0 = ex2(s[rb][2*kbl    ][0]);
                    const float p1 = ex2(s[rb][2*kbl    ][1]);
                    const float p2 = ex2(s[rb][2*kbl    ][2]);
                    const float p3 = ex2(s[rb][2*kbl    ][3]);
                    const float p4 = ex2(s[rb][2*kbl + 1][0]);
                    const float p5 = ex2(s[rb][2*kbl + 1][1]);
                    const float p6 = ex2(s[rb][2*kbl + 1][2]);
                    const float p7 = ex2(s[rb][2*kbl + 1][3]);
                    L_lo[rb] += (p0 + p1) + (p4 + p5);
                    L_hi[rb] += (p2 + p3) + (p6 + p7);
                    a0[rb] = pk2(p0, p1);
                    a1[rb] = pk2(p2, p3);
                    a2[rb] = pk2(p4, p5);
                    a3[rb] = pk2(p6, p7);
                }
                const int kbg = 2 * hf + kbl;
                #pragma unroll
                for (int np = 0; np < 4; ++np) {
                    unsigned c00, c01, c10, c11;
                    ldsm4(c00, c01, c10, c11, vfb[np] + vof + kbg * 32);
                    #pragma unroll
                    for (int rb = 0; rb < 2; ++rb) {
                        mma16(o[rb][2*np    ], a0[rb], a1[rb], a2[rb], a3[rb], c00, c01);
                        mma16(o[rb][2*np + 1], a0[rb], a1[rb], a2[rb], a3[rb], c10, c11);
                    }
                }
            }
        }
    }

    unsigned* xw = (unsigned*)g_ax;
    #pragma unroll
    for (int rb = 0; rb < 2; ++rb) {
        float ll = L_lo[rb], lh = L_hi[rb];
        ll += __shfl_xor_sync(FULL, ll, 1);
        ll += __shfl_xor_sync(FULL, ll, 2);
        lh += __shfl_xor_sync(FULL, lh, 1);
        lh += __shfl_xor_sync(FULL, lh, 2);
        const float il_lo = 1.f / ll, il_hi = 1.f / lh;
        const int r_lo = q0 + w * 32 + rb * 16 + g, r_hi = r_lo + 8;
        #pragma unroll
        for (int nt = 0; nt < 8; ++nt) {
            const int c = h * DK_ + nt * 8 + t * 2;
            xw[(((size_t)(b * S_ + r_lo)) * D_ + c) >> 1] =
                pk2(o[rb][nt][0] * il_lo, o[rb][nt][1] * il_lo);
            xw[(((size_t)(b * S_ + r_hi)) * D_ + c) >> 1] =
                pk2(o[rb][nt][2] * il_hi, o[rb][nt][3] * il_hi);
        }
    }
}

// ---------------------------------------------------------------------------
extern "C" void kernel_launch(void* const* d_in, const int* in_sizes, int n_in,
                              void* d_out, int out_size)
{
    const float* query = (const float*)d_in[0];
    const float* key   = (const float*)d_in[1];
    const float* value = (const float*)d_in[2];
    const int*   mask  = (const int*)d_in[3];
    const float* W0 = (const float*)d_in[4];
    const float* b0 = (const float*)d_in[5];
    const float* W1 = (const float*)d_in[6];
    const float* b1 = (const float*)d_in[7];
    const float* W2 = (const float*)d_in[8];
    const float* b2 = (const float*)d_in[9];
    const float* W3 = (const float*)d_in[10];
    const float* b3 = (const float*)d_in[11];
    float* out = (float*)d_out;

    cudaFuncSetAttribute(gemm_qkv, cudaFuncAttributeMaxDynamicSharedMemorySize, GEMM_SMEM);
    cudaFuncSetAttribute(gemm_fin, cudaFuncAttributeMaxDynamicSharedMemorySize, GEMM_SMEM);

    prep_all<<<16384, 256>>>(query, key, value, W0, W1, W2, W3);

    // z = 0..2: Q/K/V projections; z = 3: mask tile scan (overlapped).
    gemm_qkv<<<dim3(D_ / 128, M_ / 128, 4), 256, GEMM_SMEM>>>(b0, b1, b2, mask);

    attn_tc<<<dim3(S_ / 128, H_, B_), 128>>>(mask);

    gemm_fin<<<dim3(D_ / 128, M_ / 128), 256, GEMM_SMEM>>>(b3, out);
}

// round 15
// speedup vs baseline: 1.0417x; 1.0417x over previous
#include <cuda_runtime.h>
#include <cuda_fp16.h>
#include <math.h>

#define B_  2
#define S_  2048
#define D_  1024
#define H_  16
#define DK_ 64
#define M_  (B_*S_)   // 4096

// Scratch (device globals — no allocation allowed).
__device__ __half g_hq[M_*D_];      // fp16 copies of inputs
__device__ __half g_hk[M_*D_];
__device__ __half g_hv[M_*D_];
__device__ __half g_hw0[D_*D_];     // fp16 copies of weights
__device__ __half g_hw1[D_*D_];
__device__ __half g_hw2[D_*D_];
__device__ __half g_hw3[D_*D_];
// Projected tensors (fp16). g_q pre-scaled by 0.125*log2(e). g_q/g_k: [b,h,s,d].
// g_v: d-major [b,h,d,s] (s contiguous -> s-pair halves form one 32-bit word).
__device__ __half g_q[B_*H_*S_*DK_];
__device__ __half g_k[B_*H_*S_*DK_];
__device__ __half g_v[B_*H_*S_*DK_];
__device__ __half g_ax[M_*D_];      // attention output (fp16)
__device__ unsigned char g_mflag[B_*16*32];

#define QSCALE 0.180336880f   // 0.125 * log2(e); scores become log2-domain

// ---------------------------------------------------------------------------
__device__ __forceinline__ unsigned pk2(float lo, float hi) {
    __half2 h = __floats2half2_rn(lo, hi);
    return *reinterpret_cast<unsigned*>(&h);
}

__device__ __forceinline__ float ex2(float x) {
    float y;
    asm("ex2.approx.f32 %0, %1;" : "=f"(y) : "f"(x));
    return y;
}

__device__ __forceinline__ void mma16(float (&c)[4],
                                      unsigned a0, unsigned a1, unsigned a2, unsigned a3,
                                      unsigned b0, unsigned b1) {
    asm volatile(
        "mma.sync.aligned.m16n8k16.row.col.f32.f16.f16.f32 "
        "{%0,%1,%2,%3}, {%4,%5,%6,%7}, {%8,%9}, {%0,%1,%2,%3};"
        : "+f"(c[0]), "+f"(c[1]), "+f"(c[2]), "+f"(c[3])
        : "r"(a0), "r"(a1), "r"(a2), "r"(a3), "r"(b0), "r"(b1));
}

__device__ __forceinline__ void ldsm4(unsigned& r0, unsigned& r1, unsigned& r2, unsigned& r3,
                                      unsigned addr) {
    asm volatile("ldmatrix.sync.aligned.m8n8.x4.shared.b16 {%0,%1,%2,%3}, [%4];"
        : "=r"(r0), "=r"(r1), "=r"(r2), "=r"(r3) : "r"(addr));
}

// .cg = L2-only; these loads are consumed from smem, keep them out of L1.
#define CPA16(dst, src) asm volatile("cp.async.cg.shared.global [%0], [%1], 16;" :: "r"(dst), "l"(src))
#define CPCOMMIT()      asm volatile("cp.async.commit_group;" ::: "memory")
#define CPWAIT0()       asm volatile("cp.async.wait_group 0;" ::: "memory")
#define CPWAIT1()       asm volatile("cp.async.wait_group 1;" ::: "memory")

// ---------------------------------------------------------------------------
// prep: fp32 -> fp16 convert only (mask scan fused into gemm_qkv z=3 slice).
// ---------------------------------------------------------------------------
__global__ __launch_bounds__(256)
void prep_all(const float* __restrict__ q, const float* __restrict__ k,
              const float* __restrict__ v,
              const float* __restrict__ W0, const float* __restrict__ W1,
              const float* __restrict__ W2, const float* __restrict__ W3)
{
    const size_t i4 = (size_t)blockIdx.x * 256 + threadIdx.x;
    const size_t off = i4 * 4;
    const size_t IN = (size_t)M_ * D_;
    const size_t WN = (size_t)D_ * D_;
    const float* src; __half* dst; size_t o;
    if      (off < IN)            { src = q;  dst = g_hq;  o = off; }
    else if (off < 2*IN)          { src = k;  dst = g_hk;  o = off - IN; }
    else if (off < 3*IN)          { src = v;  dst = g_hv;  o = off - 2*IN; }
    else if (off < 3*IN + WN)     { src = W0; dst = g_hw0; o = off - 3*IN; }
    else if (off < 3*IN + 2*WN)   { src = W1; dst = g_hw1; o = off - 3*IN - WN; }
    else if (off < 3*IN + 3*WN)   { src = W2; dst = g_hw2; o = off - 3*IN - 2*WN; }
    else                          { src = W3; dst = g_hw3; o = off - 3*IN - 3*WN; }
    float4 vv = *(const float4*)(src + o);
    *(uint2*)(dst + o) = make_uint2(pk2(vv.x, vv.y), pk2(vv.z, vv.w));
}

// ---------------------------------------------------------------------------
// FP16 NT GEMM, cp.async.cg 3-stage pipeline, K-chunk 64 (16 chunks).
// MODE: 0 = fp32 [m][n]; 1 = Q half *QSCALE; 2 = K half; 3 = V d-major [b,h,d,s].
// ---------------------------------------------------------------------------
#define GW 36                                       // 32 data words + 4 pad
#define GST (128*GW)                                // words per tile-stage
#define GNS 3
#define GEMM_SMEM (2*GNS*GST*(int)sizeof(unsigned)) // 110592 B

template<int MODE>
__device__ __forceinline__ void gemm_body(
    const __half* __restrict__ X, const __half* __restrict__ W,
    const float* __restrict__ bias, void* outp)
{
    extern __shared__ unsigned gsm[];
    unsigned* As = gsm;
    unsigned* Bs = gsm + GNS * GST;

    const int tid = threadIdx.x;
    const int lane = tid & 31, wid = tid >> 5;
    const int warpM = wid >> 2, warpN = wid & 3;
    const int m0 = blockIdx.y * 128, n0 = blockIdx.x * 128;
    const int g = lane >> 2, t = lane & 3;

    const unsigned asb = (unsigned)__cvta_generic_to_shared(As);
    const unsigned bsb = (unsigned)__cvta_generic_to_shared(Bs);

    const int selA = lane >> 3;
    const int rA = (lane & 7) + ((selA & 1) << 3);
    const int cA = selA >> 1;
    const int selB = lane >> 3;
    const int rB = lane & 7;
    const int ntOff = selB >> 1, kcB = selB & 1;

    float acc[4][4][4] = {};

    auto load_stage = [&](int c0, int st) {
        #pragma unroll
        for (int i = 0; i < 4; ++i) {
            const int idx = tid + i * 256;             // 0..1023 chunks / matrix
            const int r = idx >> 3, ch = idx & 7;
            const unsigned doff = (unsigned)(st * GST + r * GW + ch * 4) * 4;
            CPA16(asb + doff, X + (size_t)(m0 + r) * D_ + c0 * 64 + ch * 8);
            CPA16(bsb + doff, W + (size_t)(n0 + r) * D_ + c0 * 64 + ch * 8);
        }
        CPCOMMIT();
    };

    load_stage(0, 0);
    load_stage(1, 1);

    for (int c0 = 0; c0 < 16; ++c0) {
        if (c0 < 14) CPWAIT1(); else CPWAIT0();     // chunk c0 resident
        __syncthreads();
        if (c0 + 2 < 16) {
            int st = c0 + 2; while (st >= GNS) st -= GNS;   // (c0+2) % 3
            load_stage(c0 + 2, st);
        }

        int cs = c0; while (cs >= GNS) cs -= GNS;           // c0 % 3
        const unsigned ab = asb + (unsigned)(cs * GST) * 4;
        const unsigned bb = bsb + (unsigned)(cs * GST) * 4;

        #pragma unroll
        for (int kb = 0; kb < 4; ++kb) {
            unsigned af[4][4], bf[4][2];
            #pragma unroll
            for (int mt = 0; mt < 4; ++mt) {
                const unsigned addr = ab +
                    (unsigned)((warpM * 64 + mt * 16 + rA) * GW + cA * 4 + kb * 8) * 4;
                ldsm4(af[mt][0], af[mt][1], af[mt][2], af[mt][3], addr);
            }
            #pragma unroll
            for (int np = 0; np < 2; ++np) {
                const unsigned addr = bb +
                    (unsigned)((warpN * 32 + (np * 2 + ntOff) * 8 + rB) * GW + kcB * 4 + kb * 8) * 4;
                ldsm4(bf[np*2][0], bf[np*2][1], bf[np*2+1][0], bf[np*2+1][1], addr);
            }
            #pragma unroll
            for (int mt = 0; mt < 4; ++mt)
                #pragma unroll
                for (int nt = 0; nt < 4; ++nt)
                    mma16(acc[mt][nt], af[mt][0], af[mt][1], af[mt][2], af[mt][3],
                          bf[nt][0], bf[nt][1]);
        }
    }

    #pragma unroll
    for (int mt = 0; mt < 4; ++mt) {
        const int r_lo = m0 + warpM * 64 + mt * 16 + g;
        const int r_hi = r_lo + 8;
        #pragma unroll
        for (int nt = 0; nt < 4; ++nt) {
            const int col = n0 + warpN * 32 + nt * 8 + t * 2;
            const float bv0 = bias[col], bv1 = bias[col + 1];
            float v0 = acc[mt][nt][0] + bv0, v1 = acc[mt][nt][1] + bv1;
            float v2 = acc[mt][nt][2] + bv0, v3 = acc[mt][nt][3] + bv1;
            if (MODE == 0) {
                float* out = (float*)outp;
                *(float2*)&out[(size_t)r_lo * D_ + col] = make_float2(v0, v1);
                *(float2*)&out[(size_t)r_hi * D_ + col] = make_float2(v2, v3);
            } else {
                const int h = col >> 6, d = col & 63;
                if (MODE == 1) { v0 *= QSCALE; v1 *= QSCALE; v2 *= QSCALE; v3 *= QSCALE; }
                const int s_lo = r_lo & 2047, s_hi = r_hi & 2047;
                const size_t bh_lo = (size_t)((r_lo >> 11) * H_ + h);
                const size_t bh_hi = (size_t)((r_hi >> 11) * H_ + h);
                if (MODE == 1 || MODE == 2) {
                    unsigned* out = (unsigned*)outp;
                    out[((bh_lo * S_ + s_lo) * DK_ + d) >> 1] = pk2(v0, v1);
                    out[((bh_hi * S_ + s_hi) * DK_ + d) >> 1] = pk2(v2, v3);
                } else {   // MODE 3: V d-major [b,h,d,s]
                    __half* out = (__half*)outp;
                    const size_t base_lo = bh_lo * (S_ * DK_);
                    const size_t base_hi = bh_hi * (S_ * DK_);
                    out[base_lo + (size_t)d       * S_ + s_lo] = __float2half_rn(v0);
                    out[base_lo + (size_t)(d + 1) * S_ + s_lo] = __float2half_rn(v1);
                    out[base_hi + (size_t)d       * S_ + s_hi] = __float2half_rn(v2);
                    out[base_hi + (size_t)(d + 1) * S_ + s_hi] = __float2half_rn(v3);
                }
            }
        }
    }
}

// z in [0,2]: Q/K/V projections. z==3: mask tile scan (4 tiles per block),
// overlapped with the tensor-bound GEMM wave.
__global__ __launch_bounds__(256, 2)
void gemm_qkv(const float* __restrict__ b0, const float* __restrict__ b1,
              const float* __restrict__ b2, const int* __restrict__ mask)
{
    const int z = blockIdx.z;
    if (z == 3) {
        const int base_idx = (blockIdx.y * 8 + blockIdx.x) * 4;
        for (int i = 0; i < 4; ++i) {
            const int tile = base_idx + i;             // b*512 + qt*32 + kt
            const int kt = tile & 31, qt = (tile >> 5) & 15, b = tile >> 9;
            const int* basep = mask + ((size_t)(b * S_) + qt * 128) * S_ + kt * 64;
            int ok = 1;
            for (int j = threadIdx.x; j < 2048; j += 256) {
                const int r = j >> 4, c = (j & 15) * 4;
                int4 vv = *(const int4*)(basep + (size_t)r * S_ + c);
                ok &= (vv.x != 0) & (vv.y != 0) & (vv.z != 0) & (vv.w != 0);
            }
            ok = __syncthreads_and(ok);
            if (threadIdx.x == 0) g_mflag[tile] = (unsigned char)ok;
        }
        return;
    }
    if (z == 0)      gemm_body<1>(g_hq, g_hw0, b0, (void*)g_q);
    else if (z == 1) gemm_body<2>(g_hk, g_hw1, b1, (void*)g_k);
    else             gemm_body<3>(g_hv, g_hw2, b2, (void*)g_v);
}

__global__ __launch_bounds__(256, 2)
void gemm_fin(const float* __restrict__ bias, float* __restrict__ out)
{
    gemm_body<0>(g_ax, g_hw3, bias, (void*)out);
}

// ---------------------------------------------------------------------------
// Flash attention (R13 form): fp16 m16n8k16, log2-domain scores,
// 2-stage cp.async.cg, 4 warps x 32 q-rows, flags prefetched.
// ---------------------------------------------------------------------------
#define KST 36
#define VST 36
#define KSTG (64*KST)
#define VSTG (64*VST)

__global__ __launch_bounds__(128, 2)
void attn_tc(const int* __restrict__ mask)
{
    __shared__ unsigned Ks[2 * KSTG];
    __shared__ unsigned Vs[2 * VSTG];

    const int qt = blockIdx.x, h = blockIdx.y, b = blockIdx.z;
    const int q0 = qt * 128;
    const int tid = threadIdx.x, lane = tid & 31, w = tid >> 5;   // w: 0..3
    const int g = lane >> 2, t = lane & 3;
    const unsigned FULL = 0xffffffffu;

    const unsigned* Qw = (const unsigned*)g_q + ((size_t)(b * H_ + h) * S_ + q0 + w * 32) * 32;
    const unsigned* Kw = (const unsigned*)g_k + (size_t)(b * H_ + h) * S_ * 32;
    const unsigned* Vw = (const unsigned*)g_v + (size_t)(b * H_ + h) * S_ * 32;

    const unsigned ksb = (unsigned)__cvta_generic_to_shared(Ks);
    const unsigned vsb = (unsigned)__cvta_generic_to_shared(Vs);

    const int lrow = lane & 7;
    const int lmat = lane >> 3;
    const int ntof = lmat >> 1;
    const int bsel = lmat & 1;
    unsigned kfb[4], vfb[4];
    #pragma unroll
    for (int np = 0; np < 4; ++np) {
        kfb[np] = ksb + (unsigned)(((np * 16 + ntof * 8 + lrow) * KST + bsel * 4) * 4);
        vfb[np] = vsb + (unsigned)(((np * 16 + ntof * 8 + lrow) * VST + bsel * 4) * 4);
    }

    const int fbase = (b * 16 + qt) * 32;
    unsigned mflags[8];
    {
        const uint4* mfp = (const uint4*)&g_mflag[fbase];
        uint4 f0 = mfp[0], f1 = mfp[1];
        mflags[0] = f0.x; mflags[1] = f0.y; mflags[2] = f0.z; mflags[3] = f0.w;
        mflags[4] = f1.x; mflags[5] = f1.y; mflags[6] = f1.z; mflags[7] = f1.w;
    }

    unsigned qa[2][4][4];
    #pragma unroll
    for (int rb = 0; rb < 2; ++rb) {
        #pragma unroll
        for (int kb = 0; kb < 4; ++kb) {
            qa[rb][kb][0] = Qw[(size_t)(rb * 16 + g    ) * 32 + kb * 8 + t];
            qa[rb][kb][1] = Qw[(size_t)(rb * 16 + g + 8) * 32 + kb * 8 + t];
            qa[rb][kb][2] = Qw[(size_t)(rb * 16 + g    ) * 32 + kb * 8 + t + 4];
            qa[rb][kb][3] = Qw[(size_t)(rb * 16 + g + 8) * 32 + kb * 8 + t + 4];
        }
    }

    float o[2][8][4] = {};
    float L_lo[2] = {0.f, 0.f}, L_hi[2] = {0.f, 0.f};

    auto load_tile = [&](int kt, int st) {
        #pragma unroll
        for (int i = 0; i < 4; ++i) {
            const int idx = tid + i * 128;
            const int r = idx >> 3, ch = idx & 7;
            CPA16(ksb + (unsigned)((st * KSTG + r * KST + ch * 4) * 4),
                  Kw + (size_t)(kt * 64 + r) * 32 + ch * 4);
        }
        #pragma unroll
        for (int i = 0; i < 4; ++i) {
            const int idx = tid + i * 128;
            const int r = idx >> 3, ch = idx & 7;
            CPA16(vsb + (unsigned)((st * VSTG + r * VST + ch * 4) * 4),
                  Vw + (size_t)r * (S_ / 2) + kt * 32 + ch * 4);
        }
        CPCOMMIT();
    };

    load_tile(0, 0);

    for (int kt = 0; kt < 32; ++kt) {
        CPWAIT0();
        __syncthreads();
        if (kt < 31) load_tile(kt + 1, (kt + 1) & 1);

        const unsigned kof = (unsigned)((kt & 1) * KSTG * 4);
        const unsigned vof = (unsigned)((kt & 1) * VSTG * 4);

        float s[2][8][4] = {};
        #pragma unroll
        for (int kb = 0; kb < 4; ++kb) {
            #pragma unroll
            for (int np = 0; np < 4; ++np) {
                unsigned b00, b01, b10, b11;
                ldsm4(b00, b01, b10, b11, kfb[np] + kof + kb * 32);
                #pragma unroll
                for (int rb = 0; rb < 2; ++rb) {
                    mma16(s[rb][2*np    ], qa[rb][kb][0], qa[rb][kb][1],
                          qa[rb][kb][2], qa[rb][kb][3], b00, b01);
                    mma16(s[rb][2*np + 1], qa[rb][kb][0], qa[rb][kb][1],
                          qa[rb][kb][2], qa[rb][kb][3], b10, b11);
                }
            }
        }

        if (((mflags[kt >> 2] >> ((kt & 3) * 8)) & 0xffu) == 0) {
            const int* mb = mask + (size_t)b * S_ * S_;
            #pragma unroll
            for (int rb = 0; rb < 2; ++rb) {
                const int r_lo = q0 + w * 32 + rb * 16 + g, r_hi = r_lo + 8;
                #pragma unroll
                for (int nt = 0; nt < 8; ++nt) {
                    const int col = kt * 64 + nt * 8 + t * 2;
                    if (mb[(size_t)r_lo * S_ + col    ] == 0) s[rb][nt][0] = -1.0e9f;
                    if (mb[(size_t)r_lo * S_ + col + 1] == 0) s[rb][nt][1] = -1.0e9f;
                    if (mb[(size_t)r_hi * S_ + col    ] == 0) s[rb][nt][2] = -1.0e9f;
                    if (mb[(size_t)r_hi * S_ + col + 1] == 0) s[rb][nt][3] = -1.0e9f;
                }
            }
        }

        #pragma unroll
        for (int kb = 0; kb < 4; ++kb) {
            unsigned a0[2], a1[2], a2[2], a3[2];
            #pragma unroll
            for (int rb = 0; rb < 2; ++rb) {
                const float p0 = ex2(s[rb][2*kb    ][0]);
                const float p1 = ex2(s[rb][2*kb    ][1]);
                const float p2 = ex2(s[rb][2*kb    ][2]);
                const float p3 = ex2(s[rb][2*kb    ][3]);
                const float p4 = ex2(s[rb][2*kb + 1][0]);
                const float p5 = ex2(s[rb][2*kb + 1][1]);
                const float p6 = ex2(s[rb][2*kb + 1][2]);
                const float p7 = ex2(s[rb][2*kb + 1][3]);
                L_lo[rb] += (p0 + p1) + (p4 + p5);
                L_hi[rb] += (p2 + p3) + (p6 + p7);
                a0[rb] = pk2(p0, p1);
                a1[rb] = pk2(p2, p3);
                a2[rb] = pk2(p4, p5);
                a3[rb] = pk2(p6, p7);
            }
            #pragma unroll
            for (int np = 0; np < 4; ++np) {
                unsigned c00, c01, c10, c11;
                ldsm4(c00, c01, c10, c11, vfb[np] + vof + kb * 32);
                #pragma unroll
                for (int rb = 0; rb < 2; ++rb) {
                    mma16(o[rb][2*np    ], a0[rb], a1[rb], a2[rb], a3[rb], c00, c01);
                    mma16(o[rb][2*np + 1], a0[rb], a1[rb], a2[rb], a3[rb], c10, c11);
                }
            }
        }
    }

    unsigned* xw = (unsigned*)g_ax;
    #pragma unroll
    for (int rb = 0; rb < 2; ++rb) {
        float ll = L_lo[rb], lh = L_hi[rb];
        ll += __shfl_xor_sync(FULL, ll, 1);
        ll += __shfl_xor_sync(FULL, ll, 2);
        lh += __shfl_xor_sync(FULL, lh, 1);
        lh += __shfl_xor_sync(FULL, lh, 2);
        const float il_lo = 1.f / ll, il_hi = 1.f / lh;
        const int r_lo = q0 + w * 32 + rb * 16 + g, r_hi = r_lo + 8;
        #pragma unroll
        for (int nt = 0; nt < 8; ++nt) {
            const int c = h * DK_ + nt * 8 + t * 2;
            xw[(((size_t)(b * S_ + r_lo)) * D_ + c) >> 1] =
                pk2(o[rb][nt][0] * il_lo, o[rb][nt][1] * il_lo);
            xw[(((size_t)(b * S_ + r_hi)) * D_ + c) >> 1] =
                pk2(o[rb][nt][2] * il_hi, o[rb][nt][3] * il_hi);
        }
    }
}

// ---------------------------------------------------------------------------
extern "C" void kernel_launch(void* const* d_in, const int* in_sizes, int n_in,
                              void* d_out, int out_size)
{
    const float* query = (const float*)d_in[0];
    const float* key   = (const float*)d_in[1];
    const float* value = (const float*)d_in[2];
    const int*   mask  = (const int*)d_in[3];
    const float* W0 = (const float*)d_in[4];
    const float* b0 = (const float*)d_in[5];
    const float* W1 = (const float*)d_in[6];
    const float* b1 = (const float*)d_in[7];
    const float* W2 = (const float*)d_in[8];
    const float* b2 = (const float*)d_in[9];
    const float* W3 = (const float*)d_in[10];
    const float* b3 = (const float*)d_in[11];
    float* out = (float*)d_out;

    cudaFuncSetAttribute(gemm_qkv, cudaFuncAttributeMaxDynamicSharedMemorySize, GEMM_SMEM);
    cudaFuncSetAttribute(gemm_fin, cudaFuncAttributeMaxDynamicSharedMemorySize, GEMM_SMEM);

    prep_all<<<16384, 256>>>(query, key, value, W0, W1, W2, W3);

    // z = 0..2: Q/K/V projections; z = 3: mask tile scan (overlapped).
    gemm_qkv<<<dim3(D_ / 128, M_ / 128, 4), 256, GEMM_SMEM>>>(b0, b1, b2, mask);

    attn_tc<<<dim3(S_ / 128, H_, B_), 128>>>(mask);

    gemm_fin<<<dim3(D_ / 128, M_ / 128), 256, GEMM_SMEM>>>(b3, out);
}

// round 16
// speedup vs baseline: 1.0488x; 1.0068x over previous
#include <cuda_runtime.h>
#include <cuda_fp16.h>
#include <math.h>

#define B_  2
#define S_  2048
#define D_  1024
#define H_  16
#define DK_ 64
#define M_  (B_*S_)   // 4096

// Scratch (device globals — no allocation allowed).
__device__ __half g_hq[M_*D_];      // fp16 copies of inputs
__device__ __half g_hk[M_*D_];
__device__ __half g_hv[M_*D_];
__device__ __half g_hw0[D_*D_];     // fp16 copies of weights
__device__ __half g_hw1[D_*D_];
__device__ __half g_hw2[D_*D_];
__device__ __half g_hw3[D_*D_];
// Projected tensors (fp16). g_q pre-scaled by 0.125*log2(e). g_q/g_k: [b,h,s,d].
// g_v: d-major [b,h,d,s] (s contiguous -> s-pair halves form one 32-bit word).
__device__ __half g_q[B_*H_*S_*DK_];
__device__ __half g_k[B_*H_*S_*DK_];
__device__ __half g_v[B_*H_*S_*DK_];
__device__ __half g_ax[M_*D_];      // attention output (fp16)
__device__ unsigned char g_mflag[B_*16*32];

#define QSCALE 0.180336880f   // 0.125 * log2(e); scores become log2-domain
#define SNEG  -100.0f         // masked score (exact fp16; 2^-100 -> fp16 0)
#define ONESH2 0x3C003C00u    // half2(1.0, 1.0)

// ---------------------------------------------------------------------------
__device__ __forceinline__ unsigned pk2(float lo, float hi) {
    __half2 h = __floats2half2_rn(lo, hi);
    return *reinterpret_cast<unsigned*>(&h);
}

// pack two fp32 (log2-domain) to half2, then 2^x in fp16x2 -> PV a-frag word
__device__ __forceinline__ unsigned ex2h2(float lo, float hi) {
    unsigned pr, r;
    asm("cvt.rn.f16x2.f32 %0, %1, %2;" : "=r"(pr) : "f"(hi), "f"(lo));
    asm("ex2.approx.f16x2 %0, %1;" : "=r"(r) : "r"(pr));
    return r;
}

__device__ __forceinline__ void mma16(float (&c)[4],
                                      unsigned a0, unsigned a1, unsigned a2, unsigned a3,
                                      unsigned b0, unsigned b1) {
    asm volatile(
        "mma.sync.aligned.m16n8k16.row.col.f32.f16.f16.f32 "
        "{%0,%1,%2,%3}, {%4,%5,%6,%7}, {%8,%9}, {%0,%1,%2,%3};"
        : "+f"(c[0]), "+f"(c[1]), "+f"(c[2]), "+f"(c[3])
        : "r"(a0), "r"(a1), "r"(a2), "r"(a3), "r"(b0), "r"(b1));
}

__device__ __forceinline__ void ldsm4(unsigned& r0, unsigned& r1, unsigned& r2, unsigned& r3,
                                      unsigned addr) {
    asm volatile("ldmatrix.sync.aligned.m8n8.x4.shared.b16 {%0,%1,%2,%3}, [%4];"
        : "=r"(r0), "=r"(r1), "=r"(r2), "=r"(r3) : "r"(addr));
}

// .cg = L2-only; these loads are consumed from smem, keep them out of L1.
#define CPA16(dst, src) asm volatile("cp.async.cg.shared.global [%0], [%1], 16;" :: "r"(dst), "l"(src))
#define CPCOMMIT()      asm volatile("cp.async.commit_group;" ::: "memory")
#define CPWAIT0()       asm volatile("cp.async.wait_group 0;" ::: "memory")
#define CPWAIT1()       asm volatile("cp.async.wait_group 1;" ::: "memory")

// ---------------------------------------------------------------------------
// prep: fp32 -> fp16 convert only (mask scan fused into gemm_qkv z=3 slice).
// ---------------------------------------------------------------------------
__global__ __launch_bounds__(256)
void prep_all(const float* __restrict__ q, const float* __restrict__ k,
              const float* __restrict__ v,
              const float* __restrict__ W0, const float* __restrict__ W1,
              const float* __restrict__ W2, const float* __restrict__ W3)
{
    const size_t i4 = (size_t)blockIdx.x * 256 + threadIdx.x;
    const size_t off = i4 * 4;
    const size_t IN = (size_t)M_ * D_;
    const size_t WN = (size_t)D_ * D_;
    const float* src; __half* dst; size_t o;
    if      (off < IN)            { src = q;  dst = g_hq;  o = off; }
    else if (off < 2*IN)          { src = k;  dst = g_hk;  o = off - IN; }
    else if (off < 3*IN)          { src = v;  dst = g_hv;  o = off - 2*IN; }
    else if (off < 3*IN + WN)     { src = W0; dst = g_hw0; o = off - 3*IN; }
    else if (off < 3*IN + 2*WN)   { src = W1; dst = g_hw1; o = off - 3*IN - WN; }
    else if (off < 3*IN + 3*WN)   { src = W2; dst = g_hw2; o = off - 3*IN - 2*WN; }
    else                          { src = W3; dst = g_hw3; o = off - 3*IN - 3*WN; }
    float4 vv = *(const float4*)(src + o);
    *(uint2*)(dst + o) = make_uint2(pk2(vv.x, vv.y), pk2(vv.z, vv.w));
}

// ---------------------------------------------------------------------------
// FP16 NT GEMM, cp.async.cg 3-stage pipeline, K-chunk 64 (16 chunks).
// MODE: 0 = fp32 [m][n]; 1 = Q half *QSCALE; 2 = K half; 3 = V d-major [b,h,d,s].
// ---------------------------------------------------------------------------
#define GW 36                                       // 32 data words + 4 pad
#define GST (128*GW)                                // words per tile-stage
#define GNS 3
#define GEMM_SMEM (2*GNS*GST*(int)sizeof(unsigned)) // 110592 B

template<int MODE>
__device__ __forceinline__ void gemm_body(
    const __half* __restrict__ X, const __half* __restrict__ W,
    const float* __restrict__ bias, void* outp)
{
    extern __shared__ unsigned gsm[];
    unsigned* As = gsm;
    unsigned* Bs = gsm + GNS * GST;

    const int tid = threadIdx.x;
    const int lane = tid & 31, wid = tid >> 5;
    const int warpM = wid >> 2, warpN = wid & 3;
    const int m0 = blockIdx.y * 128, n0 = blockIdx.x * 128;
    const int g = lane >> 2, t = lane & 3;

    const unsigned asb = (unsigned)__cvta_generic_to_shared(As);
    const unsigned bsb = (unsigned)__cvta_generic_to_shared(Bs);

    const int selA = lane >> 3;
    const int rA = (lane & 7) + ((selA & 1) << 3);
    const int cA = selA >> 1;
    const int selB = lane >> 3;
    const int rB = lane & 7;
    const int ntOff = selB >> 1, kcB = selB & 1;

    float acc[4][4][4] = {};

    auto load_stage = [&](int c0, int st) {
        #pragma unroll
        for (int i = 0; i < 4; ++i) {
            const int idx = tid + i * 256;             // 0..1023 chunks / matrix
            const int r = idx >> 3, ch = idx & 7;
            const unsigned doff = (unsigned)(st * GST + r * GW + ch * 4) * 4;
            CPA16(asb + doff, X + (size_t)(m0 + r) * D_ + c0 * 64 + ch * 8);
            CPA16(bsb + doff, W + (size_t)(n0 + r) * D_ + c0 * 64 + ch * 8);
        }
        CPCOMMIT();
    };

    load_stage(0, 0);
    load_stage(1, 1);

    for (int c0 = 0; c0 < 16; ++c0) {
        if (c0 < 14) CPWAIT1(); else CPWAIT0();     // chunk c0 resident
        __syncthreads();
        if (c0 + 2 < 16) {
            int st = c0 + 2; while (st >= GNS) st -= GNS;   // (c0+2) % 3
            load_stage(c0 + 2, st);
        }

        int cs = c0; while (cs >= GNS) cs -= GNS;           // c0 % 3
        const unsigned ab = asb + (unsigned)(cs * GST) * 4;
        const unsigned bb = bsb + (unsigned)(cs * GST) * 4;

        #pragma unroll
        for (int kb = 0; kb < 4; ++kb) {
            unsigned af[4][4], bf[4][2];
            #pragma unroll
            for (int mt = 0; mt < 4; ++mt) {
                const unsigned addr = ab +
                    (unsigned)((warpM * 64 + mt * 16 + rA) * GW + cA * 4 + kb * 8) * 4;
                ldsm4(af[mt][0], af[mt][1], af[mt][2], af[mt][3], addr);
            }
            #pragma unroll
            for (int np = 0; np < 2; ++np) {
                const unsigned addr = bb +
                    (unsigned)((warpN * 32 + (np * 2 + ntOff) * 8 + rB) * GW + kcB * 4 + kb * 8) * 4;
                ldsm4(bf[np*2][0], bf[np*2][1], bf[np*2+1][0], bf[np*2+1][1], addr);
            }
            #pragma unroll
            for (int mt = 0; mt < 4; ++mt)
                #pragma unroll
                for (int nt = 0; nt < 4; ++nt)
                    mma16(acc[mt][nt], af[mt][0], af[mt][1], af[mt][2], af[mt][3],
                          bf[nt][0], bf[nt][1]);
        }
    }

    #pragma unroll
    for (int mt = 0; mt < 4; ++mt) {
        const int r_lo = m0 + warpM * 64 + mt * 16 + g;
        const int r_hi = r_lo + 8;
        #pragma unroll
        for (int nt = 0; nt < 4; ++nt) {
            const int col = n0 + warpN * 32 + nt * 8 + t * 2;
            const float bv0 = bias[col], bv1 = bias[col + 1];
            float v0 = acc[mt][nt][0] + bv0, v1 = acc[mt][nt][1] + bv1;
            float v2 = acc[mt][nt][2] + bv0, v3 = acc[mt][nt][3] + bv1;
            if (MODE == 0) {
                float* out = (float*)outp;
                *(float2*)&out[(size_t)r_lo * D_ + col] = make_float2(v0, v1);
                *(float2*)&out[(size_t)r_hi * D_ + col] = make_float2(v2, v3);
            } else {
                const int h = col >> 6, d = col & 63;
                if (MODE == 1) { v0 *= QSCALE; v1 *= QSCALE; v2 *= QSCALE; v3 *= QSCALE; }
                const int s_lo = r_lo & 2047, s_hi = r_hi & 2047;
                const size_t bh_lo = (size_t)((r_lo >> 11) * H_ + h);
                const size_t bh_hi = (size_t)((r_hi >> 11) * H_ + h);
                if (MODE == 1 || MODE == 2) {
                    unsigned* out = (unsigned*)outp;
                    out[((bh_lo * S_ + s_lo) * DK_ + d) >> 1] = pk2(v0, v1);
                    out[((bh_hi * S_ + s_hi) * DK_ + d) >> 1] = pk2(v2, v3);
                } else {   // MODE 3: V d-major [b,h,d,s]
                    __half* out = (__half*)outp;
                    const size_t base_lo = bh_lo * (S_ * DK_);
                    const size_t base_hi = bh_hi * (S_ * DK_);
                    out[base_lo + (size_t)d       * S_ + s_lo] = __float2half_rn(v0);
                    out[base_lo + (size_t)(d + 1) * S_ + s_lo] = __float2half_rn(v1);
                    out[base_hi + (size_t)d       * S_ + s_hi] = __float2half_rn(v2);
                    out[base_hi + (size_t)(d + 1) * S_ + s_hi] = __float2half_rn(v3);
                }
            }
        }
    }
}

// z in [0,2]: Q/K/V projections. z==3: mask tile scan (4 tiles per block),
// overlapped with the tensor-bound GEMM wave.
__global__ __launch_bounds__(256, 2)
void gemm_qkv(const float* __restrict__ b0, const float* __restrict__ b1,
              const float* __restrict__ b2, const int* __restrict__ mask)
{
    const int z = blockIdx.z;
    if (z == 3) {
        const int base_idx = (blockIdx.y * 8 + blockIdx.x) * 4;
        for (int i = 0; i < 4; ++i) {
            const int tile = base_idx + i;             // b*512 + qt*32 + kt
            const int kt = tile & 31, qt = (tile >> 5) & 15, b = tile >> 9;
            const int* basep = mask + ((size_t)(b * S_) + qt * 128) * S_ + kt * 64;
            int ok = 1;
            for (int j = threadIdx.x; j < 2048; j += 256) {
                const int r = j >> 4, c = (j & 15) * 4;
                int4 vv = *(const int4*)(basep + (size_t)r * S_ + c);
                ok &= (vv.x != 0) & (vv.y != 0) & (vv.z != 0) & (vv.w != 0);
            }
            ok = __syncthreads_and(ok);
            if (threadIdx.x == 0) g_mflag[tile] = (unsigned char)ok;
        }
        return;
    }
    if (z == 0)      gemm_body<1>(g_hq, g_hw0, b0, (void*)g_q);
    else if (z == 1) gemm_body<2>(g_hk, g_hw1, b1, (void*)g_k);
    else             gemm_body<3>(g_hv, g_hw2, b2, (void*)g_v);
}

__global__ __launch_bounds__(256, 2)
void gemm_fin(const float* __restrict__ bias, float* __restrict__ out)
{
    gemm_body<0>(g_ax, g_hw3, bias, (void*)out);
}

// ---------------------------------------------------------------------------
// Flash attention: fp16 m16n8k16, log2-domain scores, 2-stage cp.async.cg,
// 4 warps x 32 q-rows. exp via ex2.approx.f16x2 (results ARE PV a-frags);
// L accumulated by an extra ones-column MMA (fp32 accum, no FADDs/shuffles,
// and denominator uses exactly the fp16-rounded p's the numerator uses).
// ---------------------------------------------------------------------------
#define KST 36
#define VST 36
#define KSTG (64*KST)
#define VSTG (64*VST)

__global__ __launch_bounds__(128, 2)
void attn_tc(const int* __restrict__ mask)
{
    __shared__ unsigned Ks[2 * KSTG];
    __shared__ unsigned Vs[2 * VSTG];

    const int qt = blockIdx.x, h = blockIdx.y, b = blockIdx.z;
    const int q0 = qt * 128;
    const int tid = threadIdx.x, lane = tid & 31, w = tid >> 5;   // w: 0..3
    const int g = lane >> 2, t = lane & 3;

    const unsigned* Qw = (const unsigned*)g_q + ((size_t)(b * H_ + h) * S_ + q0 + w * 32) * 32;
    const unsigned* Kw = (const unsigned*)g_k + (size_t)(b * H_ + h) * S_ * 32;
    const unsigned* Vw = (const unsigned*)g_v + (size_t)(b * H_ + h) * S_ * 32;

    const unsigned ksb = (unsigned)__cvta_generic_to_shared(Ks);
    const unsigned vsb = (unsigned)__cvta_generic_to_shared(Vs);

    const int lrow = lane & 7;
    const int lmat = lane >> 3;
    const int ntof = lmat >> 1;
    const int bsel = lmat & 1;
    unsigned kfb[4], vfb[4];
    #pragma unroll
    for (int np = 0; np < 4; ++np) {
        kfb[np] = ksb + (unsigned)(((np * 16 + ntof * 8 + lrow) * KST + bsel * 4) * 4);
        vfb[np] = vsb + (unsigned)(((np * 16 + ntof * 8 + lrow) * VST + bsel * 4) * 4);
    }

    const int fbase = (b * 16 + qt) * 32;
    unsigned mflags[8];
    {
        const uint4* mfp = (const uint4*)&g_mflag[fbase];
        uint4 f0 = mfp[0], f1 = mfp[1];
        mflags[0] = f0.x; mflags[1] = f0.y; mflags[2] = f0.z; mflags[3] = f0.w;
        mflags[4] = f1.x; mflags[5] = f1.y; mflags[6] = f1.z; mflags[7] = f1.w;
    }

    unsigned qa[2][4][4];
    #pragma unroll
    for (int rb = 0; rb < 2; ++rb) {
        #pragma unroll
        for (int kb = 0; kb < 4; ++kb) {
            qa[rb][kb][0] = Qw[(size_t)(rb * 16 + g    ) * 32 + kb * 8 + t];
            qa[rb][kb][1] = Qw[(size_t)(rb * 16 + g + 8) * 32 + kb * 8 + t];
            qa[rb][kb][2] = Qw[(size_t)(rb * 16 + g    ) * 32 + kb * 8 + t + 4];
            qa[rb][kb][3] = Qw[(size_t)(rb * 16 + g + 8) * 32 + kb * 8 + t + 4];
        }
    }

    float o[2][8][4] = {};
    float lc[2][4] = {};                 // ones-MMA accumulator: L in c0/c2

    auto load_tile = [&](int kt, int st) {
        #pragma unroll
        for (int i = 0; i < 4; ++i) {
            const int idx = tid + i * 128;
            const int r = idx >> 3, ch = idx & 7;
            CPA16(ksb + (unsigned)((st * KSTG + r * KST + ch * 4) * 4),
                  Kw + (size_t)(kt * 64 + r) * 32 + ch * 4);
        }
        #pragma unroll
        for (int i = 0; i < 4; ++i) {
            const int idx = tid + i * 128;
            const int r = idx >> 3, ch = idx & 7;
            CPA16(vsb + (unsigned)((st * VSTG + r * VST + ch * 4) * 4),
                  Vw + (size_t)r * (S_ / 2) + kt * 32 + ch * 4);
        }
        CPCOMMIT();
    };

    load_tile(0, 0);

    for (int kt = 0; kt < 32; ++kt) {
        CPWAIT0();
        __syncthreads();
        if (kt < 31) load_tile(kt + 1, (kt + 1) & 1);

        const unsigned kof = (unsigned)((kt & 1) * KSTG * 4);
        const unsigned vof = (unsigned)((kt & 1) * VSTG * 4);

        float s[2][8][4] = {};
        #pragma unroll
        for (int kb = 0; kb < 4; ++kb) {
            #pragma unroll
            for (int np = 0; np < 4; ++np) {
                unsigned b00, b01, b10, b11;
                ldsm4(b00, b01, b10, b11, kfb[np] + kof + kb * 32);
                #pragma unroll
                for (int rb = 0; rb < 2; ++rb) {
                    mma16(s[rb][2*np    ], qa[rb][kb][0], qa[rb][kb][1],
                          qa[rb][kb][2], qa[rb][kb][3], b00, b01);
                    mma16(s[rb][2*np + 1], qa[rb][kb][0], qa[rb][kb][1],
                          qa[rb][kb][2], qa[rb][kb][3], b10, b11);
                }
            }
        }

        if (((mflags[kt >> 2] >> ((kt & 3) * 8)) & 0xffu) == 0) {
            const int* mb = mask + (size_t)b * S_ * S_;
            #pragma unroll
            for (int rb = 0; rb < 2; ++rb) {
                const int r_lo = q0 + w * 32 + rb * 16 + g, r_hi = r_lo + 8;
                #pragma unroll
                for (int nt = 0; nt < 8; ++nt) {
                    const int col = kt * 64 + nt * 8 + t * 2;
                    if (mb[(size_t)r_lo * S_ + col    ] == 0) s[rb][nt][0] = SNEG;
                    if (mb[(size_t)r_lo * S_ + col + 1] == 0) s[rb][nt][1] = SNEG;
                    if (mb[(size_t)r_hi * S_ + col    ] == 0) s[rb][nt][2] = SNEG;
                    if (mb[(size_t)r_hi * S_ + col + 1] == 0) s[rb][nt][3] = SNEG;
                }
            }
        }

        // exp2 in fp16x2 -> PV a-frags; L via ones-column MMA (fp32 accum).
        #pragma unroll
        for (int kb = 0; kb < 4; ++kb) {
            unsigned a0[2], a1[2], a2[2], a3[2];
            #pragma unroll
            for (int rb = 0; rb < 2; ++rb) {
                a0[rb] = ex2h2(s[rb][2*kb    ][0], s[rb][2*kb    ][1]);
                a1[rb] = ex2h2(s[rb][2*kb    ][2], s[rb][2*kb    ][3]);
                a2[rb] = ex2h2(s[rb][2*kb + 1][0], s[rb][2*kb + 1][1]);
                a3[rb] = ex2h2(s[rb][2*kb + 1][2], s[rb][2*kb + 1][3]);
                mma16(lc[rb], a0[rb], a1[rb], a2[rb], a3[rb], ONESH2, ONESH2);
            }
            #pragma unroll
            for (int np = 0; np < 4; ++np) {
                unsigned c00, c01, c10, c11;
                ldsm4(c00, c01, c10, c11, vfb[np] + vof + kb * 32);
                #pragma unroll
                for (int rb = 0; rb < 2; ++rb) {
                    mma16(o[rb][2*np    ], a0[rb], a1[rb], a2[rb], a3[rb], c00, c01);
                    mma16(o[rb][2*np + 1], a0[rb], a1[rb], a2[rb], a3[rb], c10, c11);
                }
            }
        }
    }

    // L is complete in lc (MMA reduced over k): c0 = row g, c2 = row g+8.
    unsigned* xw = (unsigned*)g_ax;
    #pragma unroll
    for (int rb = 0; rb < 2; ++rb) {
        const float il_lo = 1.f / lc[rb][0];
        const float il_hi = 1.f / lc[rb][2];
        const int r_lo = q0 + w * 32 + rb * 16 + g, r_hi = r_lo + 8;
        #pragma unroll
        for (int nt = 0; nt < 8; ++nt) {
            const int c = h * DK_ + nt * 8 + t * 2;
            xw[(((size_t)(b * S_ + r_lo)) * D_ + c) >> 1] =
                pk2(o[rb][nt][0] * il_lo, o[rb][nt][1] * il_lo);
            xw[(((size_t)(b * S_ + r_hi)) * D_ + c) >> 1] =
                pk2(o[rb][nt][2] * il_hi, o[rb][nt][3] * il_hi);
        }
    }
}

// ---------------------------------------------------------------------------
extern "C" void kernel_launch(void* const* d_in, const int* in_sizes, int n_in,
                              void* d_out, int out_size)
{
    const float* query = (const float*)d_in[0];
    const float* key   = (const float*)d_in[1];
    const float* value = (const float*)d_in[2];
    const int*   mask  = (const int*)d_in[3];
    const float* W0 = (const float*)d_in[4];
    const float* b0 = (const float*)d_in[5];
    const float* W1 = (const float*)d_in[6];
    const float* b1 = (const float*)d_in[7];
    const float* W2 = (const float*)d_in[8];
    const float* b2 = (const float*)d_in[9];
    const float* W3 = (const float*)d_in[10];
    const float* b3 = (const float*)d_in[11];
    float* out = (float*)d_out;

    cudaFuncSetAttribute(gemm_qkv, cudaFuncAttributeMaxDynamicSharedMemorySize, GEMM_SMEM);
    cudaFuncSetAttribute(gemm_fin, cudaFuncAttributeMaxDynamicSharedMemorySize, GEMM_SMEM);

    prep_all<<<16384, 256>>>(query, key, value, W0, W1, W2, W3);

    // z = 0..2: Q/K/V projections; z = 3: mask tile scan (overlapped).
    gemm_qkv<<<dim3(D_ / 128, M_ / 128, 4), 256, GEMM_SMEM>>>(b0, b1, b2, mask);

    attn_tc<<<dim3(S_ / 128, H_, B_), 128>>>(mask);

    gemm_fin<<<dim3(D_ / 128, M_ / 128), 256, GEMM_SMEM>>>(b3, out);
}

// round 17
// speedup vs baseline: 1.0601x; 1.0108x over previous
#include <cuda_runtime.h>
#include <cuda_fp16.h>
#include <math.h>

#define B_  2
#define S_  2048
#define D_  1024
#define H_  16
#define DK_ 64
#define M_  (B_*S_)   // 4096

// Scratch (device globals — no allocation allowed).
__device__ __half g_hq[M_*D_];      // fp16 copies of inputs
__device__ __half g_hk[M_*D_];
__device__ __half g_hv[M_*D_];
__device__ __half g_hw0[D_*D_];     // fp16 copies of weights
__device__ __half g_hw1[D_*D_];
__device__ __half g_hw2[D_*D_];
__device__ __half g_hw3[D_*D_];
// Projected tensors (fp16). g_q pre-scaled by 0.125*log2(e). g_q/g_k: [b,h,s,d].
// g_v: d-major [b,h,d,s] (s contiguous -> s-pair halves form one 32-bit word).
__device__ __half g_q[B_*H_*S_*DK_];
__device__ __half g_k[B_*H_*S_*DK_];
__device__ __half g_v[B_*H_*S_*DK_];
__device__ __half g_ax[M_*D_];      // attention output (fp16)
__device__ unsigned char g_mflag[B_*16*32];

#define QSCALE 0.180336880f   // 0.125 * log2(e); scores become log2-domain
#define SNEG  -100.0f         // masked score (exact fp16; 2^-100 -> fp16 0)
#define ONESH2 0x3C003C00u    // half2(1.0, 1.0)

// ---------------------------------------------------------------------------
__device__ __forceinline__ unsigned pk2(float lo, float hi) {
    __half2 h = __floats2half2_rn(lo, hi);
    return *reinterpret_cast<unsigned*>(&h);
}

// pack two fp32 (log2-domain) to half2, then 2^x in fp16x2 -> PV a-frag word
__device__ __forceinline__ unsigned ex2h2(float lo, float hi) {
    unsigned pr, r;
    asm("cvt.rn.f16x2.f32 %0, %1, %2;" : "=r"(pr) : "f"(hi), "f"(lo));
    asm("ex2.approx.f16x2 %0, %1;" : "=r"(r) : "r"(pr));
    return r;
}

__device__ __forceinline__ void mma16(float (&c)[4],
                                      unsigned a0, unsigned a1, unsigned a2, unsigned a3,
                                      unsigned b0, unsigned b1) {
    asm volatile(
        "mma.sync.aligned.m16n8k16.row.col.f32.f16.f16.f32 "
        "{%0,%1,%2,%3}, {%4,%5,%6,%7}, {%8,%9}, {%0,%1,%2,%3};"
        : "+f"(c[0]), "+f"(c[1]), "+f"(c[2]), "+f"(c[3])
        : "r"(a0), "r"(a1), "r"(a2), "r"(a3), "r"(b0), "r"(b1));
}

__device__ __forceinline__ void ldsm4(unsigned& r0, unsigned& r1, unsigned& r2, unsigned& r3,
                                      unsigned addr) {
    asm volatile("ldmatrix.sync.aligned.m8n8.x4.shared.b16 {%0,%1,%2,%3}, [%4];"
        : "=r"(r0), "=r"(r1), "=r"(r2), "=r"(r3) : "r"(addr));
}

// .cg = L2-only; these loads are consumed from smem, keep them out of L1.
#define CPA16(dst, src) asm volatile("cp.async.cg.shared.global [%0], [%1], 16;" :: "r"(dst), "l"(src))
#define CPCOMMIT()      asm volatile("cp.async.commit_group;" ::: "memory")
#define CPWAIT0()       asm volatile("cp.async.wait_group 0;" ::: "memory")
#define CPWAIT1()       asm volatile("cp.async.wait_group 1;" ::: "memory")

// ---------------------------------------------------------------------------
// prep: fp32 -> fp16 convert only (mask scan fused into gemm_qkv z=3 slice).
// ---------------------------------------------------------------------------
__global__ __launch_bounds__(256)
void prep_all(const float* __restrict__ q, const float* __restrict__ k,
              const float* __restrict__ v,
              const float* __restrict__ W0, const float* __restrict__ W1,
              const float* __restrict__ W2, const float* __restrict__ W3)
{
    const size_t i4 = (size_t)blockIdx.x * 256 + threadIdx.x;
    const size_t off = i4 * 4;
    const size_t IN = (size_t)M_ * D_;
    const size_t WN = (size_t)D_ * D_;
    const float* src; __half* dst; size_t o;
    if      (off < IN)            { src = q;  dst = g_hq;  o = off; }
    else if (off < 2*IN)          { src = k;  dst = g_hk;  o = off - IN; }
    else if (off < 3*IN)          { src = v;  dst = g_hv;  o = off - 2*IN; }
    else if (off < 3*IN + WN)     { src = W0; dst = g_hw0; o = off - 3*IN; }
    else if (off < 3*IN + 2*WN)   { src = W1; dst = g_hw1; o = off - 3*IN - WN; }
    else if (off < 3*IN + 3*WN)   { src = W2; dst = g_hw2; o = off - 3*IN - 2*WN; }
    else                          { src = W3; dst = g_hw3; o = off - 3*IN - 3*WN; }
    float4 vv = *(const float4*)(src + o);
    *(uint2*)(dst + o) = make_uint2(pk2(vv.x, vv.y), pk2(vv.z, vv.w));
}

// ---------------------------------------------------------------------------
// FP16 NT GEMM, cp.async.cg 3-stage pipeline, K-chunk 64 (16 chunks).
// MODE: 0 = fp32 [m][n]; 1 = Q half *QSCALE; 2 = K half; 3 = V d-major [b,h,d,s].
// ---------------------------------------------------------------------------
#define GW 36                                       // 32 data words + 4 pad
#define GST (128*GW)                                // words per tile-stage
#define GNS 3
#define GEMM_SMEM (2*GNS*GST*(int)sizeof(unsigned)) // 110592 B

template<int MODE>
__device__ __forceinline__ void gemm_body(
    const __half* __restrict__ X, const __half* __restrict__ W,
    const float* __restrict__ bias, void* outp)
{
    extern __shared__ unsigned gsm[];
    unsigned* As = gsm;
    unsigned* Bs = gsm + GNS * GST;

    const int tid = threadIdx.x;
    const int lane = tid & 31, wid = tid >> 5;
    const int warpM = wid >> 2, warpN = wid & 3;
    const int m0 = blockIdx.y * 128, n0 = blockIdx.x * 128;
    const int g = lane >> 2, t = lane & 3;

    const unsigned asb = (unsigned)__cvta_generic_to_shared(As);
    const unsigned bsb = (unsigned)__cvta_generic_to_shared(Bs);

    const int selA = lane >> 3;
    const int rA = (lane & 7) + ((selA & 1) << 3);
    const int cA = selA >> 1;
    const int selB = lane >> 3;
    const int rB = lane & 7;
    const int ntOff = selB >> 1, kcB = selB & 1;

    float acc[4][4][4] = {};

    auto load_stage = [&](int c0, int st) {
        #pragma unroll
        for (int i = 0; i < 4; ++i) {
            const int idx = tid + i * 256;             // 0..1023 chunks / matrix
            const int r = idx >> 3, ch = idx & 7;
            const unsigned doff = (unsigned)(st * GST + r * GW + ch * 4) * 4;
            CPA16(asb + doff, X + (size_t)(m0 + r) * D_ + c0 * 64 + ch * 8);
            CPA16(bsb + doff, W + (size_t)(n0 + r) * D_ + c0 * 64 + ch * 8);
        }
        CPCOMMIT();
    };

    load_stage(0, 0);
    load_stage(1, 1);

    for (int c0 = 0; c0 < 16; ++c0) {
        if (c0 < 14) CPWAIT1(); else CPWAIT0();     // chunk c0 resident
        __syncthreads();
        if (c0 + 2 < 16) {
            int st = c0 + 2; while (st >= GNS) st -= GNS;   // (c0+2) % 3
            load_stage(c0 + 2, st);
        }

        int cs = c0; while (cs >= GNS) cs -= GNS;           // c0 % 3
        const unsigned ab = asb + (unsigned)(cs * GST) * 4;
        const unsigned bb = bsb + (unsigned)(cs * GST) * 4;

        #pragma unroll
        for (int kb = 0; kb < 4; ++kb) {
            unsigned af[4][4], bf[4][2];
            #pragma unroll
            for (int mt = 0; mt < 4; ++mt) {
                const unsigned addr = ab +
                    (unsigned)((warpM * 64 + mt * 16 + rA) * GW + cA * 4 + kb * 8) * 4;
                ldsm4(af[mt][0], af[mt][1], af[mt][2], af[mt][3], addr);
            }
            #pragma unroll
            for (int np = 0; np < 2; ++np) {
                const unsigned addr = bb +
                    (unsigned)((warpN * 32 + (np * 2 + ntOff) * 8 + rB) * GW + kcB * 4 + kb * 8) * 4;
                ldsm4(bf[np*2][0], bf[np*2][1], bf[np*2+1][0], bf[np*2+1][1], addr);
            }
            #pragma unroll
            for (int mt = 0; mt < 4; ++mt)
                #pragma unroll
                for (int nt = 0; nt < 4; ++nt)
                    mma16(acc[mt][nt], af[mt][0], af[mt][1], af[mt][2], af[mt][3],
                          bf[nt][0], bf[nt][1]);
        }
    }

    #pragma unroll
    for (int mt = 0; mt < 4; ++mt) {
        const int r_lo = m0 + warpM * 64 + mt * 16 + g;
        const int r_hi = r_lo + 8;
        #pragma unroll
        for (int nt = 0; nt < 4; ++nt) {
            const int col = n0 + warpN * 32 + nt * 8 + t * 2;
            const float bv0 = bias[col], bv1 = bias[col + 1];
            float v0 = acc[mt][nt][0] + bv0, v1 = acc[mt][nt][1] + bv1;
            float v2 = acc[mt][nt][2] + bv0, v3 = acc[mt][nt][3] + bv1;
            if (MODE == 0) {
                float* out = (float*)outp;
                *(float2*)&out[(size_t)r_lo * D_ + col] = make_float2(v0, v1);
                *(float2*)&out[(size_t)r_hi * D_ + col] = make_float2(v2, v3);
            } else {
                const int h = col >> 6, d = col & 63;
                if (MODE == 1) { v0 *= QSCALE; v1 *= QSCALE; v2 *= QSCALE; v3 *= QSCALE; }
                const int s_lo = r_lo & 2047, s_hi = r_hi & 2047;
                const size_t bh_lo = (size_t)((r_lo >> 11) * H_ + h);
                const size_t bh_hi = (size_t)((r_hi >> 11) * H_ + h);
                if (MODE == 1 || MODE == 2) {
                    unsigned* out = (unsigned*)outp;
                    out[((bh_lo * S_ + s_lo) * DK_ + d) >> 1] = pk2(v0, v1);
                    out[((bh_hi * S_ + s_hi) * DK_ + d) >> 1] = pk2(v2, v3);
                } else {   // MODE 3: V d-major [b,h,d,s]
                    __half* out = (__half*)outp;
                    const size_t base_lo = bh_lo * (S_ * DK_);
                    const size_t base_hi = bh_hi * (S_ * DK_);
                    out[base_lo + (size_t)d       * S_ + s_lo] = __float2half_rn(v0);
                    out[base_lo + (size_t)(d + 1) * S_ + s_lo] = __float2half_rn(v1);
                    out[base_hi + (size_t)d       * S_ + s_hi] = __float2half_rn(v2);
                    out[base_hi + (size_t)(d + 1) * S_ + s_hi] = __float2half_rn(v3);
                }
            }
        }
    }
}

// z in [0,2]: Q/K/V projections. z==3: mask tile scan (4 tiles per block),
// overlapped with the tensor-bound GEMM wave.
__global__ __launch_bounds__(256, 2)
void gemm_qkv(const float* __restrict__ b0, const float* __restrict__ b1,
              const float* __restrict__ b2, const int* __restrict__ mask)
{
    const int z = blockIdx.z;
    if (z == 3) {
        const int base_idx = (blockIdx.y * 8 + blockIdx.x) * 4;
        for (int i = 0; i < 4; ++i) {
            const int tile = base_idx + i;             // b*512 + qt*32 + kt
            const int kt = tile & 31, qt = (tile >> 5) & 15, b = tile >> 9;
            const int* basep = mask + ((size_t)(b * S_) + qt * 128) * S_ + kt * 64;
            int ok = 1;
            for (int j = threadIdx.x; j < 2048; j += 256) {
                const int r = j >> 4, c = (j & 15) * 4;
                int4 vv = *(const int4*)(basep + (size_t)r * S_ + c);
                ok &= (vv.x != 0) & (vv.y != 0) & (vv.z != 0) & (vv.w != 0);
            }
            ok = __syncthreads_and(ok);
            if (threadIdx.x == 0) g_mflag[tile] = (unsigned char)ok;
        }
        return;
    }
    if (z == 0)      gemm_body<1>(g_hq, g_hw0, b0, (void*)g_q);
    else if (z == 1) gemm_body<2>(g_hk, g_hw1, b1, (void*)g_k);
    else             gemm_body<3>(g_hv, g_hw2, b2, (void*)g_v);
}

__global__ __launch_bounds__(256, 2)
void gemm_fin(const float* __restrict__ bias, float* __restrict__ out)
{
    gemm_body<0>(g_ax, g_hw3, bias, (void*)out);
}

// ---------------------------------------------------------------------------
// Flash attention: fp16 m16n8k16, log2-domain scores, 2-stage cp.async.cg,
// 4 warps x 32 q-rows. 128-key tiles processed as two 64-key halves
// (halves the barrier/wait/load-issue rounds; per-half math identical).
// exp via ex2.approx.f16x2; L via ones-column MMA.
// ---------------------------------------------------------------------------
#define KST 36
#define VST 68
#define KSTG (128*KST)                 // 4608 words per K stage
#define VSTG (64*VST)                  // 4352 words per V stage
#define ATTN_SMEM (2*(KSTG+VSTG)*(int)sizeof(unsigned))   // 71680 B

__global__ __launch_bounds__(128, 2)
void attn_tc(const int* __restrict__ mask)
{
    extern __shared__ unsigned asmem[];
    unsigned* Ks = asmem;              // [2][128][KST]
    unsigned* Vs = asmem + 2 * KSTG;   // [2][64][VST]

    const int qt = blockIdx.x, h = blockIdx.y, b = blockIdx.z;
    const int q0 = qt * 128;
    const int tid = threadIdx.x, lane = tid & 31, w = tid >> 5;   // w: 0..3
    const int g = lane >> 2, t = lane & 3;

    const unsigned* Qw = (const unsigned*)g_q + ((size_t)(b * H_ + h) * S_ + q0 + w * 32) * 32;
    const unsigned* Kw = (const unsigned*)g_k + (size_t)(b * H_ + h) * S_ * 32;
    const unsigned* Vw = (const unsigned*)g_v + (size_t)(b * H_ + h) * S_ * 32;

    const unsigned ksb = (unsigned)__cvta_generic_to_shared(Ks);
    const unsigned vsb = (unsigned)__cvta_generic_to_shared(Vs);

    const int lrow = lane & 7;
    const int lmat = lane >> 3;
    const int ntof = lmat >> 1;
    const int bsel = lmat & 1;
    unsigned kfb[4], vfb[4];
    #pragma unroll
    for (int np = 0; np < 4; ++np) {
        kfb[np] = ksb + (unsigned)(((np * 16 + ntof * 8 + lrow) * KST + bsel * 4) * 4);
        vfb[np] = vsb + (unsigned)(((np * 16 + ntof * 8 + lrow) * VST + bsel * 4) * 4);
    }

    const int fbase = (b * 16 + qt) * 32;
    unsigned mflags[8];
    {
        const uint4* mfp = (const uint4*)&g_mflag[fbase];
        uint4 f0 = mfp[0], f1 = mfp[1];
        mflags[0] = f0.x; mflags[1] = f0.y; mflags[2] = f0.z; mflags[3] = f0.w;
        mflags[4] = f1.x; mflags[5] = f1.y; mflags[6] = f1.z; mflags[7] = f1.w;
    }

    unsigned qa[2][4][4];
    #pragma unroll
    for (int rb = 0; rb < 2; ++rb) {
        #pragma unroll
        for (int kb = 0; kb < 4; ++kb) {
            qa[rb][kb][0] = Qw[(size_t)(rb * 16 + g    ) * 32 + kb * 8 + t];
            qa[rb][kb][1] = Qw[(size_t)(rb * 16 + g + 8) * 32 + kb * 8 + t];
            qa[rb][kb][2] = Qw[(size_t)(rb * 16 + g    ) * 32 + kb * 8 + t + 4];
            qa[rb][kb][3] = Qw[(size_t)(rb * 16 + g + 8) * 32 + kb * 8 + t + 4];
        }
    }

    float o[2][8][4] = {};
    float lc[2][4] = {};                 // ones-MMA accumulator: L in c0/c2

    // 128-key tile loader: K 128 rows x 8 chunks, V 64 d-rows x 16 chunks.
    auto load_tile = [&](int kt, int st) {
        #pragma unroll
        for (int i = 0; i < 8; ++i) {
            const int idx = tid + i * 128;             // 0..1023
            const int r = idx >> 3, ch = idx & 7;
            CPA16(ksb + (unsigned)((st * KSTG + r * KST + ch * 4) * 4),
                  Kw + (size_t)(kt * 128 + r) * 32 + ch * 4);
        }
        #pragma unroll
        for (int i = 0; i < 8; ++i) {
            const int idx = tid + i * 128;             // 0..1023
            const int r = idx >> 4, ch = idx & 15;     // r: d-row 0..63
            CPA16(vsb + (unsigned)((st * VSTG + r * VST + ch * 4) * 4),
                  Vw + (size_t)r * (S_ / 2) + kt * 64 + ch * 4);
        }
        CPCOMMIT();
    };

    load_tile(0, 0);

    for (int kt = 0; kt < 16; ++kt) {
        CPWAIT0();
        __syncthreads();
        if (kt < 15) load_tile(kt + 1, (kt + 1) & 1);

        const unsigned kof = (unsigned)((kt & 1) * KSTG * 4);
        const unsigned vof = (unsigned)((kt & 1) * VSTG * 4);

        #pragma unroll
        for (int hf = 0; hf < 2; ++hf) {
            const unsigned khf = kof + (unsigned)(hf * 64 * KST * 4);
            const int fidx = 2 * kt + hf;              // 64-key flag index

            // S = Q K^T for keys [kt*128 + hf*64, +64)
            float s[2][8][4] = {};
            #pragma unroll
            for (int kb = 0; kb < 4; ++kb) {
                #pragma unroll
                for (int np = 0; np < 4; ++np) {
                    unsigned b00, b01, b10, b11;
                    ldsm4(b00, b01, b10, b11, kfb[np] + khf + kb * 32);
                    #pragma unroll
                    for (int rb = 0; rb < 2; ++rb) {
                        mma16(s[rb][2*np    ], qa[rb][kb][0], qa[rb][kb][1],
                              qa[rb][kb][2], qa[rb][kb][3], b00, b01);
                        mma16(s[rb][2*np + 1], qa[rb][kb][0], qa[rb][kb][1],
                              qa[rb][kb][2], qa[rb][kb][3], b10, b11);
                    }
                }
            }

            if (((mflags[fidx >> 2] >> ((fidx & 3) * 8)) & 0xffu) == 0) {
                const int* mb = mask + (size_t)b * S_ * S_;
                #pragma unroll
                for (int rb = 0; rb < 2; ++rb) {
                    const int r_lo = q0 + w * 32 + rb * 16 + g, r_hi = r_lo + 8;
                    #pragma unroll
                    for (int nt = 0; nt < 8; ++nt) {
                        const int col = kt * 128 + hf * 64 + nt * 8 + t * 2;
                        if (mb[(size_t)r_lo * S_ + col    ] == 0) s[rb][nt][0] = SNEG;
                        if (mb[(size_t)r_lo * S_ + col + 1] == 0) s[rb][nt][1] = SNEG;
                        if (mb[(size_t)r_hi * S_ + col    ] == 0) s[rb][nt][2] = SNEG;
                        if (mb[(size_t)r_hi * S_ + col + 1] == 0) s[rb][nt][3] = SNEG;
                    }
                }
            }

            // exp2 in fp16x2 -> PV a-frags; L via ones-column MMA.
            #pragma unroll
            for (int kb = 0; kb < 4; ++kb) {
                unsigned a0[2], a1[2], a2[2], a3[2];
                #pragma unroll
                for (int rb = 0; rb < 2; ++rb) {
                    a0[rb] = ex2h2(s[rb][2*kb    ][0], s[rb][2*kb    ][1]);
                    a1[rb] = ex2h2(s[rb][2*kb    ][2], s[rb][2*kb    ][3]);
                    a2[rb] = ex2h2(s[rb][2*kb + 1][0], s[rb][2*kb + 1][1]);
                    a3[rb] = ex2h2(s[rb][2*kb + 1][2], s[rb][2*kb + 1][3]);
                    mma16(lc[rb], a0[rb], a1[rb], a2[rb], a3[rb], ONESH2, ONESH2);
                }
                const unsigned vko = vof + (unsigned)((hf * 4 + kb) * 32);
                #pragma unroll
                for (int np = 0; np < 4; ++np) {
                    unsigned c00, c01, c10, c11;
                    ldsm4(c00, c01, c10, c11, vfb[np] + vko);
                    #pragma unroll
                    for (int rb = 0; rb < 2; ++rb) {
                        mma16(o[rb][2*np    ], a0[rb], a1[rb], a2[rb], a3[rb], c00, c01);
                        mma16(o[rb][2*np + 1], a0[rb], a1[rb], a2[rb], a3[rb], c10, c11);
                    }
                }
            }
        }
    }

    // L is complete in lc (MMA reduced over k): c0 = row g, c2 = row g+8.
    unsigned* xw = (unsigned*)g_ax;
    #pragma unroll
    for (int rb = 0; rb < 2; ++rb) {
        const float il_lo = 1.f / lc[rb][0];
        const float il_hi = 1.f / lc[rb][2];
        const int r_lo = q0 + w * 32 + rb * 16 + g, r_hi = r_lo + 8;
        #pragma unroll
        for (int nt = 0; nt < 8; ++nt) {
            const int c = h * DK_ + nt * 8 + t * 2;
            xw[(((size_t)(b * S_ + r_lo)) * D_ + c) >> 1] =
                pk2(o[rb][nt][0] * il_lo, o[rb][nt][1] * il_lo);
            xw[(((size_t)(b * S_ + r_hi)) * D_ + c) >> 1] =
                pk2(o[rb][nt][2] * il_hi, o[rb][nt][3] * il_hi);
        }
    }
}

// ---------------------------------------------------------------------------
extern "C" void kernel_launch(void* const* d_in, const int* in_sizes, int n_in,
                              void* d_out, int out_size)
{
    const float* query = (const float*)d_in[0];
    const float* key   = (const float*)d_in[1];
    const float* value = (const float*)d_in[2];
    const int*   mask  = (const int*)d_in[3];
    const float* W0 = (const float*)d_in[4];
    const float* b0 = (const float*)d_in[5];
    const float* W1 = (const float*)d_in[6];
    const float* b1 = (const float*)d_in[7];
    const float* W2 = (const float*)d_in[8];
    const float* b2 = (const float*)d_in[9];
    const float* W3 = (const float*)d_in[10];
    const float* b3 = (const float*)d_in[11];
    float* out = (float*)d_out;

    cudaFuncSetAttribute(gemm_qkv, cudaFuncAttributeMaxDynamicSharedMemorySize, GEMM_SMEM);
    cudaFuncSetAttribute(gemm_fin, cudaFuncAttributeMaxDynamicSharedMemorySize, GEMM_SMEM);
    cudaFuncSetAttribute(attn_tc,  cudaFuncAttributeMaxDynamicSharedMemorySize, ATTN_SMEM);

    prep_all<<<16384, 256>>>(query, key, value, W0, W1, W2, W3);

    // z = 0..2: Q/K/V projections; z = 3: mask tile scan (overlapped).
    gemm_qkv<<<dim3(D_ / 128, M_ / 128, 4), 256, GEMM_SMEM>>>(b0, b1, b2, mask);

    attn_tc<<<dim3(S_ / 128, H_, B_), 128, ATTN_SMEM>>>(mask);

    gemm_fin<<<dim3(D_ / 128, M_ / 128), 256, GEMM_SMEM>>>(b3, out);
}